// round 6
// baseline (speedup 1.0000x reference)
#include <cuda_runtime.h>
#include <cstring>

#define VOCAB 512
#define EMBD  128
#define HID   64
#define BATCH 256
#define TLEN  1024

// Precomputed layer-0 input table: P0[v][j] = bih0[j] + bhh0[j] + emb[v] . Wih0[j]
__device__ float g_P0[VOCAB * HID];

// ---------------------------------------------------------------------------
// Kernel 1: precompute P0 (512 x 64, each a 128-dot). Trivial cost.
// ---------------------------------------------------------------------------
__global__ void precompute_P0(const float* __restrict__ emb,
                              const float* __restrict__ Wih0,
                              const float* __restrict__ bih0,
                              const float* __restrict__ bhh0)
{
    __shared__ float embs[EMBD];
    __shared__ float ws[HID * (EMBD + 1)];
    const int v = blockIdx.x;
    const int j = threadIdx.x;               // 64 threads

    embs[j]      = emb[v * EMBD + j];
    embs[j + 64] = emb[v * EMBD + j + 64];
    for (int r = 0; r < HID; r++) {
        ws[r * (EMBD + 1) + j]      = Wih0[r * EMBD + j];
        ws[r * (EMBD + 1) + j + 64] = Wih0[r * EMBD + j + 64];
    }
    __syncthreads();

    float acc = bih0[j] + bhh0[j];
    #pragma unroll
    for (int k = 0; k < EMBD; k++)
        acc += embs[k] * ws[j * (EMBD + 1) + k];
    g_P0[v * HID + j] = acc;
}

// ---------------------------------------------------------------------------
// Packed f32x2 helpers (Blackwell FFMA2 / FADD2 — PTX-only)
// ---------------------------------------------------------------------------
__device__ __forceinline__ void ffma2(unsigned long long& d,
                                      unsigned long long a,
                                      unsigned long long b)
{
    asm("fma.rn.f32x2 %0, %1, %2, %0;" : "+l"(d) : "l"(a), "l"(b));
}

__device__ __forceinline__ unsigned long long fadd2(unsigned long long a,
                                                    unsigned long long b)
{
    unsigned long long d;
    asm("add.rn.f32x2 %0, %1, %2;" : "=l"(d) : "l"(a), "l"(b));
    return d;
}

__device__ __forceinline__ float hsum2(unsigned long long a)
{
    float2 f;
    memcpy(&f, &a, 8);
    return f.x + f.y;
}

__device__ __forceinline__ float tanh_fast(float x)
{
    float y;
    asm("tanh.approx.f32 %0, %1;" : "=f"(y) : "f"(x));
    return y;
}

// ---------------------------------------------------------------------------
// One phase body (R2 semantics): given h0[p-1] (h0r), h1[p-2] (h1r),
// produce h0[p] (h0w) and h1[p-1] (h1w). Prefetches P0 for the next phase.
// All buffer pointers are compile-time-static at each call site (unrolled).
// ---------------------------------------------------------------------------
struct PhaseCtx {
    const unsigned long long* w0p;   // Whh0[u]  (32 f32x2)
    const unsigned long long* w1p;   // Wih1[u]
    const unsigned long long* w2p;   // Whh1[u]
    const float* P0s;
    const int*   xrow;
    float        c1;
    int          u;
    int          barid;
};

template<bool DO_H0, bool DO_H1>
__device__ __forceinline__ void phase_body(const PhaseCtx& ctx,
                                           const float* h0r, const float* h1r,
                                           float* h0w, float* h1w,
                                           int tnext, float& p0v)
{
    // prefetch next phase's P0 value (issued first; 58-cyc LDS chain hides
    // under the FFMA stream below)
    const int   tok = ctx.xrow[tnext];
    const float p0n = ctx.P0s[tok * HID + ctx.u];

    // ---- pass over h0[p-1]: L0 (a*) and L1a (b*) share the loads
    unsigned long long a0 = 0, a1 = 0, b0 = 0, b1 = 0;
    {
        const ulonglong2* hv2 = (const ulonglong2*)h0r;
        #pragma unroll
        for (int jj = 0; jj < 16; jj++) {
            ulonglong2 v = hv2[jj];
            ffma2(a0, v.x, ctx.w0p[2 * jj]);
            ffma2(a1, v.y, ctx.w0p[2 * jj + 1]);
            ffma2(b0, v.x, ctx.w1p[2 * jj]);
            ffma2(b1, v.y, ctx.w1p[2 * jj + 1]);
        }
    }

    // finalize h0[p] now — its reduce/tanh/STS tail overlaps L1b issue below
    if (DO_H0) {
        const float s0 = hsum2(fadd2(a0, a1));
        h0w[ctx.u] = tanh_fast(s0 + p0v);
    }

    // ---- pass over h1[p-2]: L1b (c*)
    unsigned long long c0 = 0, c1b = 0, c2 = 0, c3 = 0;
    {
        const ulonglong2* gv2 = (const ulonglong2*)h1r;
        #pragma unroll
        for (int jj = 0; jj < 16; jj += 2) {
            ulonglong2 v0 = gv2[jj];
            ffma2(c0,  v0.x, ctx.w2p[2 * jj]);
            ffma2(c1b, v0.y, ctx.w2p[2 * jj + 1]);
            ulonglong2 v1 = gv2[jj + 1];
            ffma2(c2,  v1.x, ctx.w2p[2 * jj + 2]);
            ffma2(c3,  v1.y, ctx.w2p[2 * jj + 3]);
        }
    }

    if (DO_H1) {
        const float s1 = hsum2(fadd2(fadd2(b0, b1), fadd2(fadd2(c0, c1b), fadd2(c2, c3))));
        h1w[ctx.u] = tanh_fast(s1 + ctx.c1);
    }

    p0v = p0n;
    asm volatile("bar.sync %0, 64;" :: "r"(ctx.barid) : "memory");
}

// ---------------------------------------------------------------------------
// Kernel 2: fused 2-layer RNN scan + head. Grid: 128 CTAs x 128 threads;
// CTA owns 2 batches (group g = tid>>6, 64 threads, warps {2g,2g+1} -> one
// warp per SMSP, independent named barrier per group). Thread u owns hidden
// unit u for both layers; 96 weight f32x2 registers. Phase loop unrolled x2
// with peeled first/last phases -> static buffer pointers, no selects.
// ---------------------------------------------------------------------------
__global__ __launch_bounds__(128, 1)
void rnn_scan_kernel(const int*   __restrict__ x,
                     const float* __restrict__ Whh0,
                     const float* __restrict__ Wih1,
                     const float* __restrict__ Whh1,
                     const float* __restrict__ bih1,
                     const float* __restrict__ bhh1,
                     const float* __restrict__ W1,
                     const float* __restrict__ b1,
                     const float* __restrict__ W2,
                     const float* __restrict__ b2,
                     float*       __restrict__ out)
{
    extern __shared__ float smem[];
    // layout: P0s[VOCAB*HID] | xs[2*TLEN] (int) | hbuf[2*256]
    float* P0s  = smem;
    int*   xs   = (int*)(smem + VOCAB * HID);
    float* hbuf = smem + VOCAB * HID + 2 * TLEN;

    const int tid  = threadIdx.x;
    const int g    = tid >> 6;       // batch group within CTA
    const int u    = tid & 63;       // hidden unit
    const int bidx = blockIdx.x * 2 + g;

    // ---- stage P0 table (float4), token rows; zero h buffers
    {
        const float4* srcp = (const float4*)g_P0;
        float4*       dstp = (float4*)P0s;
        for (int i = tid; i < (VOCAB * HID) / 4; i += 128) dstp[i] = srcp[i];
    }
    for (int i = tid; i < 2 * TLEN; i += 128)
        xs[i] = x[(blockIdx.x * 2 + (i >> 10)) * TLEN + (i & (TLEN - 1))];
    for (int i = tid; i < 512; i += 128) hbuf[i] = 0.0f;

    // ---- pack weights into 64-bit f32x2 registers (96 u64 = 192 floats)
    unsigned long long w0p[32], w1p[32], w2p[32];
    {
        const unsigned long long* a  = (const unsigned long long*)(Whh0 + u * HID);
        const unsigned long long* bq = (const unsigned long long*)(Wih1 + u * HID);
        const unsigned long long* c  = (const unsigned long long*)(Whh1 + u * HID);
        #pragma unroll
        for (int k = 0; k < 32; k++) { w0p[k] = a[k]; w1p[k] = bq[k]; w2p[k] = c[k]; }
    }

    __syncthreads();

    // per-group buffers: h0[2], h1[2] (64 floats each)
    float* base = hbuf + g * 256;
    float* h0A = base;        // even-phase read / odd-phase write
    float* h0B = base + 64;   // even-phase write / odd-phase read
    float* h1A = base + 128;
    float* h1B = base + 192;

    PhaseCtx ctx;
    ctx.w0p = w0p; ctx.w1p = w1p; ctx.w2p = w2p;
    ctx.P0s = P0s; ctx.xrow = xs + g * TLEN;
    ctx.c1  = bih1[u] + bhh1[u];
    ctx.u   = u; ctx.barid = 1 + g;

    // ---- phase 0 (peeled): h0[0] = tanh(P0[x0]); h1[-1] stays 0 (pre-zeroed)
    float p0v = P0s[ctx.xrow[0] * HID + u];
    h0B[u] = tanh_fast(p0v);
    p0v = P0s[ctx.xrow[1] * HID + u];
    asm volatile("bar.sync %0, 64;" :: "r"(ctx.barid) : "memory");

    // ---- main loop: phases 1..1022 as 511 unrolled pairs (odd, even)
    for (int i = 0; i < 511; i++) {
        // odd phase p = 2i+1: read B, write A
        phase_body<true, true>(ctx, h0B, h1B, h0A, h1A, 2 * i + 2, p0v);
        // even phase p = 2i+2: read A, write B
        phase_body<true, true>(ctx, h0A, h1A, h0B, h1B, 2 * i + 3, p0v);
    }

    // ---- phase 1023 (odd): read B, write A
    phase_body<true, true>(ctx, h0B, h1B, h0A, h1A, TLEN - 1, p0v);
    // ---- phase 1024 (even): only h1[1023]; read A, write B
    phase_body<false, true>(ctx, h0A, h1A, h0B, h1B, TLEN - 1, p0v);

    // h1[T-1] is in h1B
    const float* h1f = h1B;

    // ---- head: y = relu(h1f @ W1^T + b1) @ W2^T + b2  (first warp of group)
    if (u < 32) {
        float acc = b1[u];
        #pragma unroll
        for (int k = 0; k < HID; k++)
            acc += W1[u * HID + k] * h1f[k];
        acc = fmaxf(acc, 0.0f);
        float s = acc * W2[u];
        #pragma unroll
        for (int off = 16; off; off >>= 1)
            s += __shfl_down_sync(0xffffffffu, s, off);
        if (u == 0) out[bidx] = s + b2[0];
    }
}

// ---------------------------------------------------------------------------
extern "C" void kernel_launch(void* const* d_in, const int* in_sizes, int n_in,
                              void* d_out, int out_size)
{
    const int*   x    = (const int*)  d_in[0];
    const float* emb  = (const float*)d_in[1];
    const float* Wih0 = (const float*)d_in[2];
    const float* Whh0 = (const float*)d_in[3];
    const float* bih0 = (const float*)d_in[4];
    const float* bhh0 = (const float*)d_in[5];
    const float* Wih1 = (const float*)d_in[6];
    const float* Whh1 = (const float*)d_in[7];
    const float* bih1 = (const float*)d_in[8];
    const float* bhh1 = (const float*)d_in[9];
    const float* W1   = (const float*)d_in[10];
    const float* b1   = (const float*)d_in[11];
    const float* W2   = (const float*)d_in[12];
    const float* b2   = (const float*)d_in[13];
    float* out = (float*)d_out;

    precompute_P0<<<VOCAB, 64>>>(emb, Wih0, bih0, bhh0);

    const int smem_bytes = (VOCAB * HID + 2 * TLEN + 512) * 4;  // 141,312 B
    cudaFuncSetAttribute(rnn_scan_kernel,
                         cudaFuncAttributeMaxDynamicSharedMemorySize, smem_bytes);
    rnn_scan_kernel<<<BATCH / 2, 128, smem_bytes>>>(
        x, Whh0, Wih1, Whh1, bih1, bhh1, W1, b1, W2, b2, out);
}

// round 7
// speedup vs baseline: 1.6768x; 1.6768x over previous
#include <cuda_runtime.h>
#include <cstring>

#define VOCAB 512
#define EMBD  128
#define HID   64
#define BATCH 256
#define TLEN  1024

// Precomputed layer-0 input table: P0[v][j] = bih0[j] + bhh0[j] + emb[v] . Wih0[j]
__device__ float g_P0[VOCAB * HID];

// ---------------------------------------------------------------------------
// Kernel 1: precompute P0 (512 x 64, each a 128-dot). Trivial cost.
// ---------------------------------------------------------------------------
__global__ void precompute_P0(const float* __restrict__ emb,
                              const float* __restrict__ Wih0,
                              const float* __restrict__ bih0,
                              const float* __restrict__ bhh0)
{
    __shared__ float embs[EMBD];
    __shared__ float ws[HID * (EMBD + 1)];
    const int v = blockIdx.x;
    const int j = threadIdx.x;               // 64 threads

    embs[j]      = emb[v * EMBD + j];
    embs[j + 64] = emb[v * EMBD + j + 64];
    for (int r = 0; r < HID; r++) {
        ws[r * (EMBD + 1) + j]      = Wih0[r * EMBD + j];
        ws[r * (EMBD + 1) + j + 64] = Wih0[r * EMBD + j + 64];
    }
    __syncthreads();

    float acc = bih0[j] + bhh0[j];
    #pragma unroll
    for (int k = 0; k < EMBD; k++)
        acc += embs[k] * ws[j * (EMBD + 1) + k];
    g_P0[v * HID + j] = acc;
}

// ---------------------------------------------------------------------------
// Packed f32x2 helpers (Blackwell FFMA2 / FADD2 — PTX-only)
// ---------------------------------------------------------------------------
__device__ __forceinline__ void ffma2(unsigned long long& d,
                                      unsigned long long a,
                                      unsigned long long b)
{
    asm("fma.rn.f32x2 %0, %1, %2, %0;" : "+l"(d) : "l"(a), "l"(b));
}

__device__ __forceinline__ unsigned long long fadd2(unsigned long long a,
                                                    unsigned long long b)
{
    unsigned long long d;
    asm("add.rn.f32x2 %0, %1, %2;" : "=l"(d) : "l"(a), "l"(b));
    return d;
}

__device__ __forceinline__ float hsum2(unsigned long long a)
{
    float2 f;
    memcpy(&f, &a, 8);
    return f.x + f.y;
}

__device__ __forceinline__ float tanh_fast(float x)
{
    float y;
    asm("tanh.approx.f32 %0, %1;" : "=f"(y) : "f"(x));
    return y;
}

// ---------------------------------------------------------------------------
// Kernel 2: fused 2-layer RNN scan + head.  (R2 structure + micro-trims)
//
// Grid: 128 CTAs x 128 threads; CTA owns 2 batches (group g = tid>>6, 64
// threads = warps {2g,2g+1}, one warp per SMSP, independent named barrier).
// Thread u owns hidden unit u for BOTH layers; 96 weight f32x2 registers.
// Phase p computes h0[p] (from h0[p-1]) and h1[p-1] (from h0[p-1], h1[p-2]).
// Buffers addressed via a single XOR-toggled float offset (no selects);
// phases 0 and TLEN peeled (no predicates in hot loop); packed fadd2
// reduction trees. One bar.sync 64 per phase.
// ---------------------------------------------------------------------------
__global__ __launch_bounds__(128, 1)
void rnn_scan_kernel(const int*   __restrict__ x,
                     const float* __restrict__ Whh0,
                     const float* __restrict__ Wih1,
                     const float* __restrict__ Whh1,
                     const float* __restrict__ bih1,
                     const float* __restrict__ bhh1,
                     const float* __restrict__ W1,
                     const float* __restrict__ b1,
                     const float* __restrict__ W2,
                     const float* __restrict__ b2,
                     float*       __restrict__ out)
{
    extern __shared__ float smem[];
    // layout: P0s[VOCAB*HID] | xs[2*TLEN] (int) | hbuf[2*256]
    float* P0s  = smem;
    int*   xs   = (int*)(smem + VOCAB * HID);
    float* hbuf = smem + VOCAB * HID + 2 * TLEN;

    const int tid  = threadIdx.x;
    const int g    = tid >> 6;       // batch group within CTA
    const int u    = tid & 63;       // hidden unit
    const int bidx = blockIdx.x * 2 + g;

    // ---- stage P0 table (float4), token rows; zero h buffers
    {
        const float4* srcp = (const float4*)g_P0;
        float4*       dstp = (float4*)P0s;
        for (int i = tid; i < (VOCAB * HID) / 4; i += 128) dstp[i] = srcp[i];
    }
    for (int i = tid; i < 2 * TLEN; i += 128)
        xs[i] = x[(blockIdx.x * 2 + (i >> 10)) * TLEN + (i & (TLEN - 1))];
    for (int i = tid; i < 512; i += 128) hbuf[i] = 0.0f;

    // ---- pack weights into 64-bit f32x2 registers (96 u64 = 192 floats)
    unsigned long long w0p[32], w1p[32], w2p[32];
    {
        const unsigned long long* a  = (const unsigned long long*)(Whh0 + u * HID);
        const unsigned long long* bq = (const unsigned long long*)(Wih1 + u * HID);
        const unsigned long long* c  = (const unsigned long long*)(Whh1 + u * HID);
        #pragma unroll
        for (int k = 0; k < 32; k++) { w0p[k] = a[k]; w1p[k] = bq[k]; w2p[k] = c[k]; }
    }
    const float c1 = bih1[u] + bhh1[u];

    __syncthreads();

    // per-group buffers (floats, relative to hb):
    //   h0 @ {0, 64}, h1 @ {128, 192}; read offset roff toggles 64<->0,
    //   write offset = roff ^ 64.
    float* hb = hbuf + g * 256;
    const int barid = 1 + g;
    const int* xrow = xs + g * TLEN;

    // ---- peeled phase 0: h0[0] = tanh(P0[tok0]); h1[-1] already zero
    hb[64 + u] = tanh_fast(P0s[xrow[0] * HID + u]);
    asm volatile("bar.sync %0, 64;" :: "r"(barid) : "memory");

    int roff = 64;   // phase 1 reads h0[0] at offset 64

    for (int p = 1; p < TLEN; p++) {
        const float* rp = hb + roff;            // h0[p-1] @ rp, h1[p-2] @ rp+128
        float*       wp = hb + (roff ^ 64);     // h0[p] target, h1[p-1] @ +128

        // token / P0 lookup (issued early; 58-cyc LDS chain hides under FFMAs)
        const float p0v = P0s[xrow[p] * HID + u];

        // ---- pass over h0[p-1]: L0 (a*) and L1a (b*) share the loads
        unsigned long long a0 = 0, a1 = 0, b0 = 0, b1 = 0;
        {
            const ulonglong2* hv2 = (const ulonglong2*)rp;
            #pragma unroll
            for (int jj = 0; jj < 16; jj++) {
                ulonglong2 v = hv2[jj];
                ffma2(a0, v.x, w0p[2 * jj]);
                ffma2(a1, v.y, w0p[2 * jj + 1]);
                ffma2(b0, v.x, w1p[2 * jj]);
                ffma2(b1, v.y, w1p[2 * jj + 1]);
            }
        }

        // finalize h0[p] — its reduce/tanh/STS tail overlaps L1b issue below
        wp[u] = tanh_fast(hsum2(fadd2(a0, a1)) + p0v);

        // ---- pass over h1[p-2]: L1b (c*)
        unsigned long long c0 = 0, c1b = 0;
        {
            const ulonglong2* gv2 = (const ulonglong2*)(rp + 128);
            #pragma unroll
            for (int jj = 0; jj < 16; jj++) {
                ulonglong2 v = gv2[jj];
                ffma2(c0,  v.x, w2p[2 * jj]);
                ffma2(c1b, v.y, w2p[2 * jj + 1]);
            }
        }

        // finalize h1[p-1]
        wp[128 + u] = tanh_fast(hsum2(fadd2(fadd2(b0, b1), fadd2(c0, c1b))) + c1);

        roff ^= 64;
        asm volatile("bar.sync %0, 64;" :: "r"(barid) : "memory");
    }

    // ---- peeled phase TLEN: only h1[T-1] = tanh(Wih1.h0[T-1] + Whh1.h1[T-2] + c1)
    // after the loop roff == 0: h0[T-1] @ hb+0, h1[T-2] @ hb+128; write h1 @ hb+192.
    {
        unsigned long long b0 = 0, b1 = 0, c0 = 0, c1b = 0;
        const ulonglong2* hv2 = (const ulonglong2*)hb;
        const ulonglong2* gv2 = (const ulonglong2*)(hb + 128);
        #pragma unroll
        for (int jj = 0; jj < 16; jj++) {
            ulonglong2 v = hv2[jj];
            ffma2(b0, v.x, w1p[2 * jj]);
            ffma2(b1, v.y, w1p[2 * jj + 1]);
            ulonglong2 w = gv2[jj];
            ffma2(c0,  w.x, w2p[2 * jj]);
            ffma2(c1b, w.y, w2p[2 * jj + 1]);
        }
        hb[192 + u] = tanh_fast(hsum2(fadd2(fadd2(b0, b1), fadd2(c0, c1b))) + c1);
    }
    asm volatile("bar.sync %0, 64;" :: "r"(barid) : "memory");

    const float* h1f = hb + 192;   // h1[T-1]

    // ---- head: y = relu(h1f @ W1^T + b1) @ W2^T + b2  (first warp of group)
    if (u < 32) {
        float acc = b1[u];
        #pragma unroll
        for (int k = 0; k < HID; k++)
            acc += W1[u * HID + k] * h1f[k];
        acc = fmaxf(acc, 0.0f);
        float s = acc * W2[u];
        #pragma unroll
        for (int off = 16; off; off >>= 1)
            s += __shfl_down_sync(0xffffffffu, s, off);
        if (u == 0) out[bidx] = s + b2[0];
    }
}

// ---------------------------------------------------------------------------
extern "C" void kernel_launch(void* const* d_in, const int* in_sizes, int n_in,
                              void* d_out, int out_size)
{
    const int*   x    = (const int*)  d_in[0];
    const float* emb  = (const float*)d_in[1];
    const float* Wih0 = (const float*)d_in[2];
    const float* Whh0 = (const float*)d_in[3];
    const float* bih0 = (const float*)d_in[4];
    const float* bhh0 = (const float*)d_in[5];
    const float* Wih1 = (const float*)d_in[6];
    const float* Whh1 = (const float*)d_in[7];
    const float* bih1 = (const float*)d_in[8];
    const float* bhh1 = (const float*)d_in[9];
    const float* W1   = (const float*)d_in[10];
    const float* b1   = (const float*)d_in[11];
    const float* W2   = (const float*)d_in[12];
    const float* b2   = (const float*)d_in[13];
    float* out = (float*)d_out;

    precompute_P0<<<VOCAB, 64>>>(emb, Wih0, bih0, bhh0);

    const int smem_bytes = (VOCAB * HID + 2 * TLEN + 512) * 4;  // 141,312 B
    cudaFuncSetAttribute(rnn_scan_kernel,
                         cudaFuncAttributeMaxDynamicSharedMemorySize, smem_bytes);
    rnn_scan_kernel<<<BATCH / 2, 128, smem_bytes>>>(
        x, Whh0, Wih1, Whh1, bih1, bhh1, W1, b1, W2, b2, out);
}

// round 8
// speedup vs baseline: 1.9103x; 1.1392x over previous
#include <cuda_runtime.h>
#include <cstring>

#define VOCAB 512
#define EMBD  128
#define HID   64
#define BATCH 256
#define TLEN  1024

// Precomputed layer-0 input table: P0[v][j] = bih0[j] + bhh0[j] + emb[v] . Wih0[j]
__device__ float g_P0[VOCAB * HID];

// ---------------------------------------------------------------------------
// Kernel 1: precompute P0 (512 x 64, each a 128-dot). Trivial cost.
// ---------------------------------------------------------------------------
__global__ void precompute_P0(const float* __restrict__ emb,
                              const float* __restrict__ Wih0,
                              const float* __restrict__ bih0,
                              const float* __restrict__ bhh0)
{
    __shared__ float embs[EMBD];
    __shared__ float ws[HID * (EMBD + 1)];
    const int v = blockIdx.x;
    const int j = threadIdx.x;               // 64 threads

    embs[j]      = emb[v * EMBD + j];
    embs[j + 64] = emb[v * EMBD + j + 64];
    for (int r = 0; r < HID; r++) {
        ws[r * (EMBD + 1) + j]      = Wih0[r * EMBD + j];
        ws[r * (EMBD + 1) + j + 64] = Wih0[r * EMBD + j + 64];
    }
    __syncthreads();

    float acc = bih0[j] + bhh0[j];
    #pragma unroll
    for (int k = 0; k < EMBD; k++)
        acc += embs[k] * ws[j * (EMBD + 1) + k];
    g_P0[v * HID + j] = acc;
}

// ---------------------------------------------------------------------------
// Packed f32x2 helpers (Blackwell FFMA2 / FADD2 — PTX-only)
// ---------------------------------------------------------------------------
__device__ __forceinline__ void ffma2(unsigned long long& d,
                                      unsigned long long a,
                                      unsigned long long b)
{
    asm("fma.rn.f32x2 %0, %1, %2, %0;" : "+l"(d) : "l"(a), "l"(b));
}

__device__ __forceinline__ unsigned long long fadd2(unsigned long long a,
                                                    unsigned long long b)
{
    unsigned long long d;
    asm("add.rn.f32x2 %0, %1, %2;" : "=l"(d) : "l"(a), "l"(b));
    return d;
}

__device__ __forceinline__ float hsum2(unsigned long long a)
{
    float2 f;
    memcpy(&f, &a, 8);
    return f.x + f.y;
}

__device__ __forceinline__ unsigned long long pack2(float lo, float hi)
{
    float2 f; f.x = lo; f.y = hi;
    unsigned long long d;
    memcpy(&d, &f, 8);
    return d;
}

__device__ __forceinline__ float tanh_fast(float x)
{
    float y;
    asm("tanh.approx.f32 %0, %1;" : "=f"(y) : "f"(x));
    return y;
}

// ---------------------------------------------------------------------------
// Kernel 2: fused 2-layer RNN scan + head.
//
// Grid: 128 CTAs x 128 threads; CTA owns 2 batches (group g = tid>>6, 64
// threads = warps {2g,2g+1}, one warp per SMSP, independent named barrier).
// Thread u owns hidden unit u for BOTH layers; 96 weight f32x2 registers.
// Phase p computes h0[p] (from h0[p-1]) and h1[p-1] (from h0[p-1], h1[p-2]).
//
// R7 scheduling: c-pass issued BEFORE h0-finalize (so the a-chain wait
// overlaps c-pass issue); biases folded into accumulator inits (p0v carried
// from the previous phase's prefetch, c1 loop-invariant); next-phase P0
// prefetched mid-phase. XOR-toggled buffers, peeled phases 0 and TLEN.
// ---------------------------------------------------------------------------
__global__ __launch_bounds__(128, 1)
void rnn_scan_kernel(const int*   __restrict__ x,
                     const float* __restrict__ Whh0,
                     const float* __restrict__ Wih1,
                     const float* __restrict__ Whh1,
                     const float* __restrict__ bih1,
                     const float* __restrict__ bhh1,
                     const float* __restrict__ W1,
                     const float* __restrict__ b1,
                     const float* __restrict__ W2,
                     const float* __restrict__ b2,
                     float*       __restrict__ out)
{
    extern __shared__ float smem[];
    // layout: P0s[VOCAB*HID] | xs[2*TLEN] (int) | hbuf[2*256]
    float* P0s  = smem;
    int*   xs   = (int*)(smem + VOCAB * HID);
    float* hbuf = smem + VOCAB * HID + 2 * TLEN;

    const int tid  = threadIdx.x;
    const int g    = tid >> 6;       // batch group within CTA
    const int u    = tid & 63;       // hidden unit
    const int bidx = blockIdx.x * 2 + g;

    // ---- stage P0 table (float4), token rows; zero h buffers
    {
        const float4* srcp = (const float4*)g_P0;
        float4*       dstp = (float4*)P0s;
        for (int i = tid; i < (VOCAB * HID) / 4; i += 128) dstp[i] = srcp[i];
    }
    for (int i = tid; i < 2 * TLEN; i += 128)
        xs[i] = x[(blockIdx.x * 2 + (i >> 10)) * TLEN + (i & (TLEN - 1))];
    for (int i = tid; i < 512; i += 128) hbuf[i] = 0.0f;

    // ---- pack weights into 64-bit f32x2 registers (96 u64 = 192 floats)
    unsigned long long w0p[32], w1p[32], w2p[32];
    {
        const unsigned long long* a  = (const unsigned long long*)(Whh0 + u * HID);
        const unsigned long long* bq = (const unsigned long long*)(Wih1 + u * HID);
        const unsigned long long* c  = (const unsigned long long*)(Whh1 + u * HID);
        #pragma unroll
        for (int k = 0; k < 32; k++) { w0p[k] = a[k]; w1p[k] = bq[k]; w2p[k] = c[k]; }
    }
    // loop-invariant layer-1 bias, packed for accumulator init
    const unsigned long long c1pack = pack2(bih1[u] + bhh1[u], 0.0f);

    __syncthreads();

    // per-group buffers (floats, relative to hb):
    //   h0 @ {0, 64}, h1 @ {128, 192}; read offset roff toggles 64<->0.
    float* hb = hbuf + g * 256;
    const int barid = 1 + g;
    const int* xrow = xs + g * TLEN;

    // ---- peeled phase 0: h0[0] = tanh(P0[tok0]); h1[-1] stays 0
    hb[64 + u] = tanh_fast(P0s[xrow[0] * HID + u]);
    float p0v = P0s[xrow[1] * HID + u];   // carried prefetch for phase 1
    asm volatile("bar.sync %0, 64;" :: "r"(barid) : "memory");

    int roff = 64;   // phase 1 reads h0[0] at offset 64

    for (int p = 1; p < TLEN; p++) {
        const float* rp = hb + roff;            // h0[p-1] @ rp, h1[p-2] @ rp+128
        float*       wp = hb + (roff ^ 64);     // h0[p] target, h1[p-1] @ +128

        // ---- pass over h0[p-1]: L0 (a*) and L1a (b*) share the loads
        // a0 carries the precomputed layer-0 input (p0v from last phase's prefetch)
        unsigned long long a0 = pack2(p0v, 0.0f), a1 = 0, b0 = 0, b1 = 0;
        {
            const ulonglong2* hv2 = (const ulonglong2*)rp;
            #pragma unroll
            for (int jj = 0; jj < 16; jj++) {
                ulonglong2 v = hv2[jj];
                ffma2(a0, v.x, w0p[2 * jj]);
                ffma2(a1, v.y, w0p[2 * jj + 1]);
                ffma2(b0, v.x, w1p[2 * jj]);
                ffma2(b1, v.y, w1p[2 * jj + 1]);
            }
        }

        // ---- prefetch next phase's P0 (60-cyc LDS chain hides under c-pass)
        const int tnext = (p + 1 < TLEN) ? (p + 1) : (TLEN - 1);
        const float p0n = P0s[xrow[tnext] * HID + u];

        // ---- pass over h1[p-2]: L1b (c*), issued BEFORE h0 finalize so the
        // a-chain completion wait overlaps this issue stream
        unsigned long long c0 = c1pack, c1b = 0;
        {
            const ulonglong2* gv2 = (const ulonglong2*)(rp + 128);
            #pragma unroll
            for (int jj = 0; jj < 16; jj++) {
                ulonglong2 v = gv2[jj];
                ffma2(c0,  v.x, w2p[2 * jj]);
                ffma2(c1b, v.y, w2p[2 * jj + 1]);
            }
        }

        // ---- finalize h0[p]  (bias already inside a0)
        wp[u] = tanh_fast(hsum2(fadd2(a0, a1)));

        // ---- finalize h1[p-1]  (bias already inside c0)
        wp[128 + u] = tanh_fast(hsum2(fadd2(fadd2(b0, b1), fadd2(c0, c1b))));

        p0v = p0n;
        roff ^= 64;
        asm volatile("bar.sync %0, 64;" :: "r"(barid) : "memory");
    }

    // ---- peeled phase TLEN: only h1[T-1] = tanh(Wih1.h0[T-1] + Whh1.h1[T-2] + c1)
    // after the loop roff == 0: h0[T-1] @ hb+0, h1[T-2] @ hb+128; write @ hb+192.
    {
        unsigned long long b0 = 0, b1 = 0, c0 = c1pack, c1b = 0;
        const ulonglong2* hv2 = (const ulonglong2*)hb;
        const ulonglong2* gv2 = (const ulonglong2*)(hb + 128);
        #pragma unroll
        for (int jj = 0; jj < 16; jj++) {
            ulonglong2 v = hv2[jj];
            ffma2(b0, v.x, w1p[2 * jj]);
            ffma2(b1, v.y, w1p[2 * jj + 1]);
            ulonglong2 w = gv2[jj];
            ffma2(c0,  w.x, w2p[2 * jj]);
            ffma2(c1b, w.y, w2p[2 * jj + 1]);
        }
        hb[192 + u] = tanh_fast(hsum2(fadd2(fadd2(b0, b1), fadd2(c0, c1b))));
    }
    asm volatile("bar.sync %0, 64;" :: "r"(barid) : "memory");

    const float* h1f = hb + 192;   // h1[T-1]

    // ---- head: y = relu(h1f @ W1^T + b1) @ W2^T + b2  (first warp of group)
    if (u < 32) {
        float acc = b1[u];
        #pragma unroll
        for (int k = 0; k < HID; k++)
            acc += W1[u * HID + k] * h1f[k];
        acc = fmaxf(acc, 0.0f);
        float s = acc * W2[u];
        #pragma unroll
        for (int off = 16; off; off >>= 1)
            s += __shfl_down_sync(0xffffffffu, s, off);
        if (u == 0) out[bidx] = s + b2[0];
    }
}

// ---------------------------------------------------------------------------
extern "C" void kernel_launch(void* const* d_in, const int* in_sizes, int n_in,
                              void* d_out, int out_size)
{
    const int*   x    = (const int*)  d_in[0];
    const float* emb  = (const float*)d_in[1];
    const float* Wih0 = (const float*)d_in[2];
    const float* Whh0 = (const float*)d_in[3];
    const float* bih0 = (const float*)d_in[4];
    const float* bhh0 = (const float*)d_in[5];
    const float* Wih1 = (const float*)d_in[6];
    const float* Whh1 = (const float*)d_in[7];
    const float* bih1 = (const float*)d_in[8];
    const float* bhh1 = (const float*)d_in[9];
    const float* W1   = (const float*)d_in[10];
    const float* b1   = (const float*)d_in[11];
    const float* W2   = (const float*)d_in[12];
    const float* b2   = (const float*)d_in[13];
    float* out = (float*)d_out;

    precompute_P0<<<VOCAB, 64>>>(emb, Wih0, bih0, bhh0);

    const int smem_bytes = (VOCAB * HID + 2 * TLEN + 512) * 4;  // 141,312 B
    cudaFuncSetAttribute(rnn_scan_kernel,
                         cudaFuncAttributeMaxDynamicSharedMemorySize, smem_bytes);
    rnn_scan_kernel<<<BATCH / 2, 128, smem_bytes>>>(
        x, Whh0, Wih1, Whh1, bih1, bhh1, W1, b1, W2, b2, out);
}